// round 3
// baseline (speedup 1.0000x reference)
#include <cuda_runtime.h>
#include <math.h>

#define HH      148
#define WWIDTH  300
#define HWPIX   44400      // 148*300
#define DDIM    128
#define MKEYS   2048
#define NBLK_PIX 174       // ceil(44400/256)

// ---------------- scratch (device globals; no allocation allowed) -----------
__device__ float g_qn[DDIM * HWPIX];          // normalized query, [c][p]
__device__ float g_qnn[HWPIX];                // ||q2d[n]||
__device__ float g_mn[MKEYS];                 // ||keys[m]||
__device__ float g_cos[(size_t)MKEYS * HWPIX];// cosine score matrix (364 MB)
__device__ float g_L[MKEYS];                  // logsumexp per memory row
__device__ int   g_i1[HWPIX];
__device__ int   g_i2[HWPIX];
__device__ float g_h1[512 * HWPIX];
__device__ float g_h2[256 * HWPIX];
__device__ float g_h3[128 * HWPIX];
__device__ float g_av[64 * HWPIX];            // a = theta_net(qn, k_w*)
__device__ float g_bv[64 * HWPIX];            // b = theta_net(qn, t_w*)
__device__ float g_partG[NBLK_PIX];
__device__ float g_partS[NBLK_PIX];

// ---------------- query normalize -------------------------------------------
__global__ __launch_bounds__(256) void qnorm_kernel(const float* __restrict__ q)
{
    int p = blockIdx.x * 256 + threadIdx.x;
    if (p >= HWPIX) return;
    float s = 0.f;
    #pragma unroll 4
    for (int c = 0; c < DDIM; ++c) { float v = q[c * HWPIX + p]; s = fmaf(v, v, s); }
    float r = sqrtf(s);
    float inv = 1.f / fmaxf(r, 1e-12f);
    #pragma unroll 4
    for (int c = 0; c < DDIM; ++c) g_qn[c * HWPIX + p] = q[c * HWPIX + p] * inv;
    g_qnn[p] = r * inv;
}

// ---------------- key norms --------------------------------------------------
__global__ void keynorm_kernel(const float* __restrict__ keys)
{
    int m = blockIdx.x * 8 + (threadIdx.x >> 5);
    int lane = threadIdx.x & 31;
    float s = 0.f;
    for (int j = lane; j < DDIM; j += 32) { float v = keys[m * DDIM + j]; s = fmaf(v, v, s); }
    #pragma unroll
    for (int o = 16; o > 0; o >>= 1) s += __shfl_xor_sync(0xffffffffu, s, o);
    if (lane == 0) g_mn[m] = sqrtf(s);
}

// ---------------- score GEMM: cos[m][n] = keys[m]·qn[:,n] / max(mn*qnn,1e-6) -
__global__ __launch_bounds__(256) void score_gemm(const float* __restrict__ keys)
{
    __shared__ float sA[16][64];   // [k][m]
    __shared__ float sB[16][64];   // [k][n]
    const int t = threadIdx.x;
    const int m0 = blockIdx.y * 64, n0 = blockIdx.x * 64;
    float acc[4][4];
    #pragma unroll
    for (int i = 0; i < 4; ++i)
        #pragma unroll
        for (int j = 0; j < 4; ++j) acc[i][j] = 0.f;
    const int tm = (t >> 4) << 2, tn = (t & 15) << 2;

    for (int k0 = 0; k0 < DDIM; k0 += 16) {
        {
            int mm = t >> 2, kk = (t & 3) << 2;
            float4 v = *(const float4*)(keys + (m0 + mm) * DDIM + k0 + kk);
            sA[kk + 0][mm] = v.x; sA[kk + 1][mm] = v.y;
            sA[kk + 2][mm] = v.z; sA[kk + 3][mm] = v.w;
        }
        #pragma unroll
        for (int rr = 0; rr < 4; ++rr) {
            int i = t + rr * 256;
            int kk = i >> 6, nn = i & 63;
            int n = n0 + nn;
            sB[kk][nn] = (n < HWPIX) ? g_qn[(k0 + kk) * HWPIX + n] : 0.f;
        }
        __syncthreads();
        #pragma unroll
        for (int k = 0; k < 16; ++k) {
            float4 a = *(const float4*)&sA[k][tm];
            float4 b = *(const float4*)&sB[k][tn];
            float av[4] = {a.x, a.y, a.z, a.w};
            float bv[4] = {b.x, b.y, b.z, b.w};
            #pragma unroll
            for (int i = 0; i < 4; ++i)
                #pragma unroll
                for (int j = 0; j < 4; ++j)
                    acc[i][j] = fmaf(av[i], bv[j], acc[i][j]);
        }
        __syncthreads();
    }
    float qs[4];
    #pragma unroll
    for (int j = 0; j < 4; ++j) { int n = n0 + tn + j; qs[j] = (n < HWPIX) ? g_qnn[n] : 1.f; }
    #pragma unroll
    for (int i = 0; i < 4; ++i) {
        float mnv = g_mn[m0 + tm + i];
        #pragma unroll
        for (int j = 0; j < 4; ++j) {
            int n = n0 + tn + j;
            if (n < HWPIX)
                g_cos[(size_t)(m0 + tm + i) * HWPIX + n] = acc[i][j] / fmaxf(mnv * qs[j], 1e-6f);
        }
    }
}

// ---------------- per-row logsumexp (no max shift needed: |cos| <= 1) --------
__global__ __launch_bounds__(256) void rowsum_kernel()
{
    __shared__ float sred[256];
    const float* cp = g_cos + (size_t)blockIdx.x * HWPIX;
    float s = 0.f;
    for (int n = threadIdx.x; n < HWPIX; n += 256) s += expf(cp[n]);
    sred[threadIdx.x] = s;
    __syncthreads();
    for (int k = 128; k > 0; k >>= 1) {
        if (threadIdx.x < k) sred[threadIdx.x] += sred[threadIdx.x + k];
        __syncthreads();
    }
    if (threadIdx.x == 0) g_L[blockIdx.x] = logf(sred[0]);
}

// ---------------- per-pixel top-2 of (cos[m,n] - L[m]) -----------------------
__global__ __launch_bounds__(256) void top2_kernel()
{
    __shared__ float sL[MKEYS];
    for (int i = threadIdx.x; i < MKEYS; i += 256) sL[i] = g_L[i];
    __syncthreads();
    int n = blockIdx.x * 256 + threadIdx.x;
    if (n >= HWPIX) return;
    float v1 = -1e30f, v2 = -1e30f;
    int i1 = 0, i2 = 0;
    const float* cp = g_cos + n;
    #pragma unroll 4
    for (int m = 0; m < MKEYS; ++m) {
        float s = cp[(size_t)m * HWPIX] - sL[m];
        if (s > v1)      { v2 = v1; i2 = i1; v1 = s; i1 = m; }
        else if (s > v2) { v2 = s; i2 = m; }
    }
    g_i1[n] = i1;
    g_i2[n] = i2;
}

// ---------------- gathering + spreading losses (deterministic partials) ------
// NOTE: replicates the reference's top2.T.reshape(N,2) scrambling:
//   flat = [top1[0..N-1], second[0..N-1]]
//   pos_idx(n) = flat[2n], neg_idx(n) = flat[2n+1]
__global__ __launch_bounds__(256) void loss_kernel(const float* __restrict__ keys)
{
    __shared__ float sg[256], ss[256];
    int n = blockIdx.x * 256 + threadIdx.x;
    float ag = 0.f, asprd = 0.f;
    if (n < HWPIX) {
        // gathering: own top-1
        int gi = g_i1[n];
        // spreading: scrambled pairing
        int pos_idx, neg_idx;
        if (n < HWPIX / 2) {
            pos_idx = g_i1[2 * n];
            neg_idx = g_i1[2 * n + 1];
        } else {
            int m2 = n - HWPIX / 2;
            pos_idx = g_i2[2 * m2];
            neg_idx = g_i2[2 * m2 + 1];
        }
        const float* kg = keys + (size_t)gi * DDIM;
        const float* kp = keys + (size_t)pos_idx * DDIM;
        const float* kn = keys + (size_t)neg_idx * DDIM;
        float s_g = 0.f, s_p = 0.f, s_n = 0.f;
        #pragma unroll 4
        for (int d = 0; d < DDIM; ++d) {
            float qv = g_qn[d * HWPIX + n];
            float a1 = qv - __ldg(kg + d);
            s_g = fmaf(a1, a1, s_g);
            float b1 = qv - __ldg(kp + d) + 1e-6f;
            s_p = fmaf(b1, b1, s_p);
            float c1 = qv - __ldg(kn + d) + 1e-6f;
            s_n = fmaf(c1, c1, s_n);
        }
        ag = s_g;
        asprd = fmaxf(sqrtf(s_p) - sqrtf(s_n) + 1.0f, 0.0f);
    }
    sg[threadIdx.x] = ag; ss[threadIdx.x] = asprd;
    __syncthreads();
    for (int k = 128; k > 0; k >>= 1) {
        if (threadIdx.x < k) {
            sg[threadIdx.x] += sg[threadIdx.x + k];
            ss[threadIdx.x] += ss[threadIdx.x + k];
        }
        __syncthreads();
    }
    if (threadIdx.x == 0) { g_partG[blockIdx.x] = sg[0]; g_partS[blockIdx.x] = ss[0]; }
}

// ---------------- direct 3x3 conv (SAME), smem tiled -------------------------
// block = 64 out channels x (8 rows x 32 cols) pixels; thread = 8 o x 8 rows
__global__ __launch_bounds__(256, 2) void conv3x3_kernel(
    const float* __restrict__ in, const float* __restrict__ wt,
    float* __restrict__ out, int C, int relu)
{
    __shared__ float s_in[8][10][34];
    __shared__ float s_w[64][8][9];
    const int lane  = threadIdx.x & 31;
    const int wrp   = threadIdx.x >> 5;
    const int x0    = blockIdx.x * 32;
    const int y0    = blockIdx.y * 8;
    const int obase = blockIdx.z * 64;

    float acc[8][8];
    #pragma unroll
    for (int o = 0; o < 8; ++o)
        #pragma unroll
        for (int r = 0; r < 8; ++r) acc[o][r] = 0.f;

    for (int c0 = 0; c0 < C; c0 += 8) {
        for (int i = threadIdx.x; i < 8 * 10 * 34; i += 256) {
            int c = i / 340, rem = i % 340, r = rem / 34, col = rem % 34;
            int y = y0 + r - 1, x = x0 + col - 1;
            float v = 0.f;
            if ((unsigned)y < (unsigned)HH && (unsigned)x < (unsigned)WWIDTH)
                v = in[(size_t)(c0 + c) * HWPIX + y * WWIDTH + x];
            s_in[c][r][col] = v;
        }
        for (int i = threadIdx.x; i < 64 * 8 * 9; i += 256) {
            int o = i / 72, rem = i % 72, c = rem / 9, k = rem % 9;
            s_w[o][c][k] = wt[((size_t)(obase + o) * C + (c0 + c)) * 9 + k];
        }
        __syncthreads();
        #pragma unroll 1
        for (int c = 0; c < 8; ++c) {
            #pragma unroll
            for (int ky = 0; ky < 3; ++ky) {
                #pragma unroll
                for (int kx = 0; kx < 3; ++kx) {
                    float wv[8], iv[8];
                    #pragma unroll
                    for (int o = 0; o < 8; ++o) wv[o] = s_w[wrp * 8 + o][c][ky * 3 + kx];
                    #pragma unroll
                    for (int r = 0; r < 8; ++r) iv[r] = s_in[c][r + ky][lane + kx];
                    #pragma unroll
                    for (int o = 0; o < 8; ++o)
                        #pragma unroll
                        for (int r = 0; r < 8; ++r)
                            acc[o][r] = fmaf(wv[o], iv[r], acc[o][r]);
                }
            }
        }
        __syncthreads();
    }

    int x = x0 + lane;
    if (x < WWIDTH) {
        #pragma unroll
        for (int o = 0; o < 8; ++o) {
            #pragma unroll
            for (int r = 0; r < 8; ++r) {
                int y = y0 + r;
                if (y < HH) {
                    float v = acc[o][r];
                    if (relu) v = fmaxf(v, 0.f);
                    out[(size_t)(obase + wrp * 8 + o) * HWPIX + y * WWIDTH + x] = v;
                }
            }
        }
    }
}

// ---------------- attention mask + cfeature ----------------------------------
__global__ __launch_bounds__(256) void atten_kernel(float* __restrict__ outcf)
{
    int p = blockIdx.x * 256 + threadIdx.x;
    if (p >= HWPIX) return;
    float num = 0.f, na = 0.f, nb = 0.f;
    #pragma unroll 4
    for (int c = 0; c < 64; ++c) {
        float a = g_av[c * HWPIX + p];
        float b = g_bv[c * HWPIX + p];
        num = fmaf(a, b, num);
        na  = fmaf(a, a, na);
        nb  = fmaf(b, b, nb);
    }
    float mask = num / fmaxf(sqrtf(na) * sqrtf(nb), 1e-6f);
    #pragma unroll 4
    for (int c = 0; c < DDIM; ++c)
        outcf[c * HWPIX + p] = mask * g_qn[c * HWPIX + p];
}

// ---------------- scalar outputs ---------------------------------------------
__global__ void finalize_kernel(float* __restrict__ out)
{
    if (threadIdx.x == 0 && blockIdx.x == 0) {
        float sg = 0.f, ss = 0.f;
        for (int i = 0; i < NBLK_PIX; ++i) { sg += g_partG[i]; ss += g_partS[i]; }
        out[(size_t)MKEYS * DDIM + (size_t)DDIM * HWPIX + 0] = sg / ((float)HWPIX * (float)DDIM);
        out[(size_t)MKEYS * DDIM + (size_t)DDIM * HWPIX + 1] = ss / (float)HWPIX;
    }
}

// ---------------- launch -----------------------------------------------------
extern "C" void kernel_launch(void* const* d_in, const int* in_sizes, int n_in,
                              void* d_out, int out_size)
{
    const float* query = (const float*)d_in[0];
    const float* keys  = (const float*)d_in[1];
    const float* t_w1  = (const float*)d_in[2];
    const float* t_w2  = (const float*)d_in[3];
    const float* t_w3  = (const float*)d_in[4];
    const float* t_w4  = (const float*)d_in[5];
    const float* k_w1  = (const float*)d_in[6];
    const float* k_w2  = (const float*)d_in[7];
    const float* k_w3  = (const float*)d_in[8];
    const float* k_w4  = (const float*)d_in[9];
    float* out = (float*)d_out;

    float *p_qn, *p_h1, *p_h2, *p_h3, *p_a, *p_b;
    cudaGetSymbolAddress((void**)&p_qn, g_qn);
    cudaGetSymbolAddress((void**)&p_h1, g_h1);
    cudaGetSymbolAddress((void**)&p_h2, g_h2);
    cudaGetSymbolAddress((void**)&p_h3, g_h3);
    cudaGetSymbolAddress((void**)&p_a,  g_av);
    cudaGetSymbolAddress((void**)&p_b,  g_bv);

    // updated_memory = keys (unchanged)
    cudaMemcpyAsync(out, keys, (size_t)MKEYS * DDIM * sizeof(float),
                    cudaMemcpyDeviceToDevice, 0);

    qnorm_kernel<<<NBLK_PIX, 256>>>(query);
    keynorm_kernel<<<MKEYS / 8, 256>>>(keys);
    score_gemm<<<dim3((HWPIX + 63) / 64, MKEYS / 64), 256>>>(keys);
    rowsum_kernel<<<MKEYS, 256>>>();
    top2_kernel<<<NBLK_PIX, 256>>>();
    loss_kernel<<<NBLK_PIX, 256>>>(keys);

    // b = theta_net(qn, t_w*)
    conv3x3_kernel<<<dim3(10, 19, 8), 256>>>(p_qn, t_w1, p_h1, 128, 1);
    conv3x3_kernel<<<dim3(10, 19, 4), 256>>>(p_h1, t_w2, p_h2, 512, 1);
    conv3x3_kernel<<<dim3(10, 19, 2), 256>>>(p_h2, t_w3, p_h3, 256, 1);
    conv3x3_kernel<<<dim3(10, 19, 1), 256>>>(p_h3, t_w4, p_b, 128, 0);
    // a = theta_net(qn, k_w*)
    conv3x3_kernel<<<dim3(10, 19, 8), 256>>>(p_qn, k_w1, p_h1, 128, 1);
    conv3x3_kernel<<<dim3(10, 19, 4), 256>>>(p_h1, k_w2, p_h2, 512, 1);
    conv3x3_kernel<<<dim3(10, 19, 2), 256>>>(p_h2, k_w3, p_h3, 256, 1);
    conv3x3_kernel<<<dim3(10, 19, 1), 256>>>(p_h3, k_w4, p_a, 128, 0);

    atten_kernel<<<NBLK_PIX, 256>>>(out + (size_t)MKEYS * DDIM);
    finalize_kernel<<<1, 1>>>(out);
}